// round 8
// baseline (speedup 1.0000x reference)
#include <cuda_runtime.h>

#define H    128
#define NN   65536
#define GG   32768
#define EE   600000
#define ROWS 32          // rows (edges/nodes) per block tile
#define RS   36          // padded row stride in floats (144B, 16B-aligned)
#define TB   64          // threads per block (4 row-groups x 16 col-groups)

typedef unsigned long long ull;

// Scratch (static __device__ — no runtime allocation)
__device__ __align__(16) float g_nf2[(size_t)NN * H];   // nf @ mm_w1_top  (32 MB)
__device__ __align__(16) float g_agg[(size_t)GG * H];   // scatter accumulator (16 MB)
__device__ float g_cnt[GG];

// ---------------------------------------------------------------------------
// Packed f32x2 helpers (FFMA2 path — sm_103a)
// ---------------------------------------------------------------------------
__device__ __forceinline__ ull pack2(float lo, float hi) {
    ull r;
    asm("mov.b64 %0, {%1,%2};" : "=l"(r) : "f"(lo), "f"(hi));
    return r;
}
__device__ __forceinline__ void unpack2(ull v, float& lo, float& hi) {
    asm("mov.b64 {%0,%1}, %2;" : "=f"(lo), "=f"(hi) : "l"(v));
}
__device__ __forceinline__ void ffma2(ull& d, ull a, ull b) {
    asm("fma.rn.f32x2 %0, %1, %2, %0;" : "+l"(d) : "l"(a), "l"(b));
}
__device__ __forceinline__ float silu_f(float x) {
    return x / (1.0f + __expf(-x));
}

// ---------------------------------------------------------------------------
// 8x8 register-tiled GEMM step.
// Thread (cg, rg): cols [cg*8, cg*8+8), rows [rg*8, rg*8+8).
// A: smem [KK][RS] (k-major, rows contiguous).  W: gmem [KK][H] row-major.
// acc[c*4+p] holds packed (C[row 2p], C[row 2p+1]) for col c.
// Per k: 2 LDS.128 + 2 LDG.128 -> 32 FFMA2.
// ---------------------------------------------------------------------------
template <int KK>
__device__ __forceinline__ void gemm8x8(const float* __restrict__ A,
                                        const float* __restrict__ W,
                                        int cbase, int rbase, ull acc[32]) {
    #pragma unroll 2
    for (int k = 0; k < KK; k++) {
        const float* Ar = A + k * RS + rbase;
        ulonglong2 a01 = *reinterpret_cast<const ulonglong2*>(Ar);
        ulonglong2 a23 = *reinterpret_cast<const ulonglong2*>(Ar + 4);
        float4 w0 = *reinterpret_cast<const float4*>(W + (size_t)k * H + cbase);
        float4 w1 = *reinterpret_cast<const float4*>(W + (size_t)k * H + cbase + 4);
        float wv[8] = {w0.x, w0.y, w0.z, w0.w, w1.x, w1.y, w1.z, w1.w};
        #pragma unroll
        for (int c = 0; c < 8; c++) {
            ull wp = pack2(wv[c], wv[c]);
            ffma2(acc[c * 4 + 0], a01.x, wp);
            ffma2(acc[c * 4 + 1], a01.y, wp);
            ffma2(acc[c * 4 + 2], a23.x, wp);
            ffma2(acc[c * 4 + 3], a23.y, wp);
        }
    }
}

__device__ __forceinline__ void init_acc(ull acc[32], const float* b, int cbase) {
    #pragma unroll
    for (int c = 0; c < 8; c++) {
        float bv = b ? b[cbase + c] : 0.0f;
        ull bb = pack2(bv, bv);
        #pragma unroll
        for (int p = 0; p < 4; p++) acc[c * 4 + p] = bb;
    }
}

// unpack acc -> C[c][rr]
__device__ __forceinline__ void unpack_all(const ull acc[32], float C[8][8]) {
    #pragma unroll
    for (int c = 0; c < 8; c++)
        #pragma unroll
        for (int p = 0; p < 4; p++)
            unpack2(acc[c * 4 + p], C[c][2 * p], C[c][2 * p + 1]);
}

__device__ __forceinline__ void silu_all(float C[8][8]) {
    #pragma unroll
    for (int c = 0; c < 8; c++)
        #pragma unroll
        for (int r = 0; r < 8; r++) C[c][r] = silu_f(C[c][r]);
}

// store C into tile T[col][row]; cg-rotation breaks the 16-way STS conflict
__device__ __forceinline__ void store_tile(const float C[8][8], float* T,
                                           int cg, int rbase) {
    int cbase = cg * 8;
    #pragma unroll
    for (int i = 0; i < 8; i++) {
        int c = (i + cg) & 7;
        float* dst = T + (cbase + c) * RS + rbase;
        #pragma unroll
        for (int p = 0; p < 4; p++)
            *reinterpret_cast<ull*>(dst + 2 * p) = pack2(C[c][2 * p], C[c][2 * p + 1]);
    }
}

// ---------------------------------------------------------------------------
// Zero the aggregation buffers
// ---------------------------------------------------------------------------
__global__ void zero_kernel() {
    size_t i = blockIdx.x * (size_t)blockDim.x + threadIdx.x;
    size_t stride = (size_t)gridDim.x * blockDim.x;
    size_t total4 = (size_t)GG * H / 4;
    float4 z = make_float4(0.f, 0.f, 0.f, 0.f);
    for (size_t p = i; p < total4; p += stride)
        reinterpret_cast<float4*>(g_agg)[p] = z;
    if (i < GG) g_cnt[i] = 0.f;
}

// ---------------------------------------------------------------------------
// Per-target edge counts
// ---------------------------------------------------------------------------
__global__ void count_kernel(const int* __restrict__ eidx) {
    int e = blockIdx.x * blockDim.x + threadIdx.x;
    if (e < EE) atomicAdd(&g_cnt[eidx[EE + e]], 1.0f);
}

// ---------------------------------------------------------------------------
// Node kernel: x -> silu(x@nm_w1+b1) -> @nm_w2+b2 -> @mm_w1_top  => g_nf2
// ---------------------------------------------------------------------------
__global__ __launch_bounds__(TB) void node_kernel(
    const float* __restrict__ x,
    const float* __restrict__ nm_w1, const float* __restrict__ nm_b1,
    const float* __restrict__ nm_w2, const float* __restrict__ nm_b2,
    const float* __restrict__ mm_w1)
{
    __shared__ __align__(16) float A[H * RS];
    __shared__ __align__(16) float B[H * RS];
    const int base = blockIdx.x * ROWS;
    const int t = threadIdx.x;
    const int cg = t & 15, rg = t >> 4;
    const int cbase = cg * 8, rbase = rg * 8;

    for (int idx = t; idx < ROWS * H; idx += TB) {
        int row = idx >> 7, col = idx & 127;
        A[col * RS + row] = x[(size_t)(base + row) * H + col];
    }
    __syncthreads();

    ull acc[32];
    float C[8][8];

    init_acc(acc, nm_b1, cbase);
    gemm8x8<H>(A, nm_w1, cbase, rbase, acc);
    unpack_all(acc, C);
    silu_all(C);
    __syncthreads();
    store_tile(C, B, cg, rbase);
    __syncthreads();

    init_acc(acc, nm_b2, cbase);
    gemm8x8<H>(B, nm_w2, cbase, rbase, acc);
    unpack_all(acc, C);
    __syncthreads();
    store_tile(C, A, cg, rbase);
    __syncthreads();

    init_acc(acc, nullptr, cbase);          // nf2 = nf @ mm_w1_top (no bias)
    gemm8x8<H>(A, mm_w1, cbase, rbase, acc);
    unpack_all(acc, C);
    #pragma unroll
    for (int rr = 0; rr < 8; rr++) {
        float* dst = g_nf2 + (size_t)(base + rbase + rr) * H + cbase;
        *reinterpret_cast<float4*>(dst)     = make_float4(C[0][rr], C[1][rr], C[2][rr], C[3][rr]);
        *reinterpret_cast<float4*>(dst + 4) = make_float4(C[4][rr], C[5][rr], C[6][rr], C[7][rr]);
    }
}

// ---------------------------------------------------------------------------
// Fused edge kernel (per 32-edge tile):
//   ea(6) -> silu(ea@em_w1+b)            [K=6]
//         -> ef = h@em_w2+b              [K=128]
//         -> m  = silu(ef@mm_w1_bot + nf2[src] + mm_b1)   [K=128]
//         -> msg = m@mm_w2+b             [K=128]
//         -> red.global.add.v4 into g_agg[tgt]
// ---------------------------------------------------------------------------
__global__ __launch_bounds__(TB) void edge_kernel(
    const int* __restrict__ eidx,
    const float* __restrict__ node_pos, const float* __restrict__ grid_pos,
    const float* __restrict__ em_w1, const float* __restrict__ em_b1,
    const float* __restrict__ em_w2, const float* __restrict__ em_b2,
    const float* __restrict__ mm_w1, const float* __restrict__ mm_b1,
    const float* __restrict__ mm_w2, const float* __restrict__ mm_b2)
{
    __shared__ __align__(16) float A[H * RS];
    __shared__ __align__(16) float B[H * RS];
    __shared__ __align__(16) float EA[6 * RS];
    __shared__ int ssrc[ROWS], stgt[ROWS];

    const int base = blockIdx.x * ROWS;
    const int t = threadIdx.x;
    const int cg = t & 15, rg = t >> 4;
    const int cbase = cg * 8, rbase = rg * 8;

    if (t < ROWS) {
        ssrc[t] = eidx[base + t];
        stgt[t] = eidx[EE + base + t];
    }
    __syncthreads();

    for (int idx = t; idx < 6 * ROWS; idx += TB) {
        int c = idx >> 5, r = idx & 31;
        EA[c * RS + r] = (c < 3) ? node_pos[(size_t)ssrc[r] * 3 + c]
                                 : grid_pos[(size_t)stgt[r] * 3 + (c - 3)];
    }
    __syncthreads();

    ull acc[32];
    float C[8][8];

    // L1: edge MLP hidden (K=6)
    init_acc(acc, em_b1, cbase);
    gemm8x8<6>(EA, em_w1, cbase, rbase, acc);
    unpack_all(acc, C);
    silu_all(C);
    store_tile(C, A, cg, rbase);
    __syncthreads();

    // L2: ef (K=128, no activation)
    init_acc(acc, em_b2, cbase);
    gemm8x8<H>(A, em_w2, cbase, rbase, acc);
    unpack_all(acc, C);
    store_tile(C, B, cg, rbase);
    __syncthreads();

    // L3: m = silu(ef@mm_w1_bot + nf2[src] + mm_b1)
    init_acc(acc, mm_b1, cbase);
    gemm8x8<H>(B, mm_w1 + (size_t)H * H, cbase, rbase, acc);
    unpack_all(acc, C);
    #pragma unroll
    for (int rr = 0; rr < 8; rr++) {
        const float* nsrc = g_nf2 + (size_t)ssrc[rbase + rr] * H + cbase;
        float4 n0 = *reinterpret_cast<const float4*>(nsrc);
        float4 n1 = *reinterpret_cast<const float4*>(nsrc + 4);
        C[0][rr] += n0.x; C[1][rr] += n0.y; C[2][rr] += n0.z; C[3][rr] += n0.w;
        C[4][rr] += n1.x; C[5][rr] += n1.y; C[6][rr] += n1.z; C[7][rr] += n1.w;
    }
    silu_all(C);
    __syncthreads();
    store_tile(C, A, cg, rbase);
    __syncthreads();

    // L4: msg = m @ mm_w2 + mm_b2  -> scatter straight from registers
    init_acc(acc, mm_b2, cbase);
    gemm8x8<H>(A, mm_w2, cbase, rbase, acc);
    unpack_all(acc, C);
    #pragma unroll
    for (int rr = 0; rr < 8; rr++) {
        float* dst = g_agg + (size_t)stgt[rbase + rr] * H + cbase;
        asm volatile("red.global.add.v4.f32 [%0], {%1,%2,%3,%4};"
                     :: "l"(dst), "f"(C[0][rr]), "f"(C[1][rr]), "f"(C[2][rr]), "f"(C[3][rr])
                     : "memory");
        asm volatile("red.global.add.v4.f32 [%0], {%1,%2,%3,%4};"
                     :: "l"(dst + 4), "f"(C[4][rr]), "f"(C[5][rr]), "f"(C[6][rr]), "f"(C[7][rr])
                     : "memory");
    }
}

// ---------------------------------------------------------------------------
// Update MLP on mean-aggregated features -> output [G,128]
// ---------------------------------------------------------------------------
__global__ __launch_bounds__(TB) void update_kernel(
    const float* __restrict__ w1, const float* __restrict__ b1,
    const float* __restrict__ w2, const float* __restrict__ b2,
    float* __restrict__ out)
{
    __shared__ __align__(16) float A[H * RS];
    __shared__ __align__(16) float B[H * RS];
    __shared__ float sc[ROWS];
    const int base = blockIdx.x * ROWS;
    const int t = threadIdx.x;
    const int cg = t & 15, rg = t >> 4;
    const int cbase = cg * 8, rbase = rg * 8;

    if (t < ROWS) {
        float c = g_cnt[base + t];
        sc[t] = 1.0f / fmaxf(c, 1.0f);
    }
    __syncthreads();

    for (int idx = t; idx < ROWS * H; idx += TB) {
        int row = idx >> 7, col = idx & 127;
        A[col * RS + row] = g_agg[(size_t)(base + row) * H + col] * sc[row];
    }
    __syncthreads();

    ull acc[32];
    float C[8][8];

    init_acc(acc, b1, cbase);
    gemm8x8<H>(A, w1, cbase, rbase, acc);
    unpack_all(acc, C);
    silu_all(C);
    __syncthreads();
    store_tile(C, B, cg, rbase);
    __syncthreads();

    init_acc(acc, b2, cbase);
    gemm8x8<H>(B, w2, cbase, rbase, acc);
    unpack_all(acc, C);
    #pragma unroll
    for (int rr = 0; rr < 8; rr++) {
        float* dst = out + (size_t)(base + rbase + rr) * H + cbase;
        *reinterpret_cast<float4*>(dst)     = make_float4(C[0][rr], C[1][rr], C[2][rr], C[3][rr]);
        *reinterpret_cast<float4*>(dst + 4) = make_float4(C[4][rr], C[5][rr], C[6][rr], C[7][rr]);
    }
}

// ---------------------------------------------------------------------------
// Launch
// ---------------------------------------------------------------------------
extern "C" void kernel_launch(void* const* d_in, const int* in_sizes, int n_in,
                              void* d_out, int out_size) {
    const float* node_features = (const float*)d_in[0];
    const float* node_pos      = (const float*)d_in[1];
    const float* grid_pos      = (const float*)d_in[2];
    const int*   edge_index    = (const int*)d_in[3];
    const float* nm_w1 = (const float*)d_in[4];
    const float* nm_b1 = (const float*)d_in[5];
    const float* nm_w2 = (const float*)d_in[6];
    const float* nm_b2 = (const float*)d_in[7];
    const float* em_w1 = (const float*)d_in[8];
    const float* em_b1 = (const float*)d_in[9];
    const float* em_w2 = (const float*)d_in[10];
    const float* em_b2 = (const float*)d_in[11];
    const float* mm_w1 = (const float*)d_in[12];
    const float* mm_b1 = (const float*)d_in[13];
    const float* mm_w2 = (const float*)d_in[14];
    const float* mm_b2 = (const float*)d_in[15];
    const float* um_w1 = (const float*)d_in[16];
    const float* um_b1 = (const float*)d_in[17];
    const float* um_w2 = (const float*)d_in[18];
    const float* um_b2 = (const float*)d_in[19];
    float* out = (float*)d_out;

    zero_kernel<<<1024, 256>>>();

    // nf2 = (silu(x@nm_w1+b1)@nm_w2+b2) @ mm_w1_top   [N,128]
    node_kernel<<<NN / ROWS, TB>>>(node_features, nm_w1, nm_b1, nm_w2, nm_b2, mm_w1);

    count_kernel<<<(EE + 255) / 256, 256>>>(edge_index);

    // fused edge pipeline + scatter
    edge_kernel<<<EE / ROWS, TB>>>(edge_index, node_pos, grid_pos,
                                   em_w1, em_b1, em_w2, em_b2,
                                   mm_w1, mm_b1, mm_w2, mm_b2);

    // update MLP on mean-aggregated features
    update_kernel<<<GG / ROWS, TB>>>(um_w1, um_b1, um_w2, um_b2, out);
}

// round 11
// speedup vs baseline: 1.1572x; 1.1572x over previous
#include <cuda_runtime.h>

#define H    128
#define NN   65536
#define GG   32768
#define EE   600000
#define ROWS 64          // rows (edges/nodes) per block tile
#define RS   68          // padded row stride in floats (272B, 16B-aligned)
#define TB   128         // threads per block: 16 col-groups x 8 row-groups

typedef unsigned long long ull;

// Scratch (static __device__ — no runtime allocation)
__device__ __align__(16) float g_nf2[(size_t)NN * H];   // nf @ mm_w1_top  (32 MB)
__device__ __align__(16) float g_agg[(size_t)GG * H];   // scatter accumulator (16 MB)
__device__ float g_cnt[GG];

// ---------------------------------------------------------------------------
// Packed f32x2 helpers (FFMA2 path — sm_103a)
// ---------------------------------------------------------------------------
__device__ __forceinline__ ull pack2(float lo, float hi) {
    ull r;
    asm("mov.b64 %0, {%1,%2};" : "=l"(r) : "f"(lo), "f"(hi));
    return r;
}
__device__ __forceinline__ void unpack2(ull v, float& lo, float& hi) {
    asm("mov.b64 {%0,%1}, %2;" : "=f"(lo), "=f"(hi) : "l"(v));
}
__device__ __forceinline__ void ffma2(ull& d, ull a, ull b) {
    asm("fma.rn.f32x2 %0, %1, %2, %0;" : "+l"(d) : "l"(a), "l"(b));
}
__device__ __forceinline__ float silu_f(float x) {
    return x / (1.0f + __expf(-x));
}

// ---------------------------------------------------------------------------
// 8x8 register-tiled GEMM step.
// Thread (cg, rg): cols [cg*8, cg*8+8), rows [rg*8, rg*8+8).
// A: smem [KK][RS] (k-major, rows contiguous).  W: gmem [KK][H] row-major.
// acc[c*4+p] holds packed (C[row 2p], C[row 2p+1]) for col c.
// Per k: 2 LDS.128 + 2 LDG.128 -> 32 FFMA2.
// ---------------------------------------------------------------------------
template <int KK>
__device__ __forceinline__ void gemm8x8(const float* __restrict__ A,
                                        const float* __restrict__ W,
                                        int cbase, int rbase, ull acc[32]) {
    #pragma unroll 2
    for (int k = 0; k < KK; k++) {
        const float* Ar = A + k * RS + rbase;
        ulonglong2 a01 = *reinterpret_cast<const ulonglong2*>(Ar);
        ulonglong2 a23 = *reinterpret_cast<const ulonglong2*>(Ar + 4);
        float4 w0 = *reinterpret_cast<const float4*>(W + (size_t)k * H + cbase);
        float4 w1 = *reinterpret_cast<const float4*>(W + (size_t)k * H + cbase + 4);
        float wv[8] = {w0.x, w0.y, w0.z, w0.w, w1.x, w1.y, w1.z, w1.w};
        #pragma unroll
        for (int c = 0; c < 8; c++) {
            ull wp = pack2(wv[c], wv[c]);
            ffma2(acc[c * 4 + 0], a01.x, wp);
            ffma2(acc[c * 4 + 1], a01.y, wp);
            ffma2(acc[c * 4 + 2], a23.x, wp);
            ffma2(acc[c * 4 + 3], a23.y, wp);
        }
    }
}

__device__ __forceinline__ void init_acc(ull acc[32], const float* b, int cbase) {
    #pragma unroll
    for (int c = 0; c < 8; c++) {
        float bv = b ? b[cbase + c] : 0.0f;
        ull bb = pack2(bv, bv);
        #pragma unroll
        for (int p = 0; p < 4; p++) acc[c * 4 + p] = bb;
    }
}

// unpack acc -> C[c][rr]
__device__ __forceinline__ void unpack_all(const ull acc[32], float C[8][8]) {
    #pragma unroll
    for (int c = 0; c < 8; c++)
        #pragma unroll
        for (int p = 0; p < 4; p++)
            unpack2(acc[c * 4 + p], C[c][2 * p], C[c][2 * p + 1]);
}

__device__ __forceinline__ void silu_all(float C[8][8]) {
    #pragma unroll
    for (int c = 0; c < 8; c++)
        #pragma unroll
        for (int r = 0; r < 8; r++) C[c][r] = silu_f(C[c][r]);
}

// store C into tile T[col][row]; cg-rotation staggers cols -> <=2-way conflict
__device__ __forceinline__ void store_tile(const float C[8][8], float* T,
                                           int cg, int rbase) {
    int cbase = cg * 8;
    #pragma unroll
    for (int i = 0; i < 8; i++) {
        int c = (i + cg) & 7;
        float* dst = T + (cbase + c) * RS + rbase;
        #pragma unroll
        for (int p = 0; p < 4; p++)
            *reinterpret_cast<ull*>(dst + 2 * p) = pack2(C[c][2 * p], C[c][2 * p + 1]);
    }
}

// ---------------------------------------------------------------------------
// Zero the aggregation buffers
// ---------------------------------------------------------------------------
__global__ void zero_kernel() {
    size_t i = blockIdx.x * (size_t)blockDim.x + threadIdx.x;
    size_t stride = (size_t)gridDim.x * blockDim.x;
    size_t total4 = (size_t)GG * H / 4;
    float4 z = make_float4(0.f, 0.f, 0.f, 0.f);
    for (size_t p = i; p < total4; p += stride)
        reinterpret_cast<float4*>(g_agg)[p] = z;
    if (i < GG) g_cnt[i] = 0.f;
}

// ---------------------------------------------------------------------------
// Per-target edge counts
// ---------------------------------------------------------------------------
__global__ void count_kernel(const int* __restrict__ eidx) {
    int e = blockIdx.x * blockDim.x + threadIdx.x;
    if (e < EE) atomicAdd(&g_cnt[eidx[EE + e]], 1.0f);
}

// ---------------------------------------------------------------------------
// Node kernel: x -> silu(x@nm_w1+b1) -> @nm_w2+b2 -> @mm_w1_top  => g_nf2
// Single smem tile; layer outputs ride in registers across barriers.
// ---------------------------------------------------------------------------
__global__ __launch_bounds__(TB, 3) void node_kernel(
    const float* __restrict__ x,
    const float* __restrict__ nm_w1, const float* __restrict__ nm_b1,
    const float* __restrict__ nm_w2, const float* __restrict__ nm_b2,
    const float* __restrict__ mm_w1)
{
    __shared__ __align__(16) float A[H * RS];
    const int base = blockIdx.x * ROWS;
    const int t = threadIdx.x;
    const int cg = t & 15, rg = t >> 4;
    const int cbase = cg * 8, rbase = rg * 8;

    for (int idx = t; idx < ROWS * H; idx += TB) {
        int row = idx >> 7, col = idx & 127;
        A[col * RS + row] = x[(size_t)(base + row) * H + col];
    }
    __syncthreads();

    ull acc[32];
    float C[8][8];

    init_acc(acc, nm_b1, cbase);
    gemm8x8<H>(A, nm_w1, cbase, rbase, acc);
    unpack_all(acc, C);
    silu_all(C);
    __syncthreads();
    store_tile(C, A, cg, rbase);
    __syncthreads();

    init_acc(acc, nm_b2, cbase);
    gemm8x8<H>(A, nm_w2, cbase, rbase, acc);
    unpack_all(acc, C);
    __syncthreads();
    store_tile(C, A, cg, rbase);
    __syncthreads();

    init_acc(acc, nullptr, cbase);          // nf2 = nf @ mm_w1_top (no bias)
    gemm8x8<H>(A, mm_w1, cbase, rbase, acc);
    unpack_all(acc, C);
    #pragma unroll
    for (int rr = 0; rr < 8; rr++) {
        float* dst = g_nf2 + (size_t)(base + rbase + rr) * H + cbase;
        *reinterpret_cast<float4*>(dst)     = make_float4(C[0][rr], C[1][rr], C[2][rr], C[3][rr]);
        *reinterpret_cast<float4*>(dst + 4) = make_float4(C[4][rr], C[5][rr], C[6][rr], C[7][rr]);
    }
}

// ---------------------------------------------------------------------------
// Fused edge kernel (per 64-edge tile):
//   ea(6) -> silu(ea@em_w1+b)            [K=6]
//         -> ef = h@em_w2+b              [K=128]
//         -> m  = silu(ef@mm_w1_bot + nf2[src] + mm_b1)   [K=128]
//         -> msg = m@mm_w2+b             [K=128]
//         -> red.global.add.v4 into g_agg[tgt]
// ---------------------------------------------------------------------------
__global__ __launch_bounds__(TB, 3) void edge_kernel(
    const int* __restrict__ eidx,
    const float* __restrict__ node_pos, const float* __restrict__ grid_pos,
    const float* __restrict__ em_w1, const float* __restrict__ em_b1,
    const float* __restrict__ em_w2, const float* __restrict__ em_b2,
    const float* __restrict__ mm_w1, const float* __restrict__ mm_b1,
    const float* __restrict__ mm_w2, const float* __restrict__ mm_b2)
{
    __shared__ __align__(16) float A[H * RS];
    __shared__ __align__(16) float EA[6 * RS];
    __shared__ int ssrc[ROWS], stgt[ROWS];

    const int base = blockIdx.x * ROWS;
    const int t = threadIdx.x;
    const int cg = t & 15, rg = t >> 4;
    const int cbase = cg * 8, rbase = rg * 8;

    if (t < ROWS) {
        ssrc[t] = eidx[base + t];
        stgt[t] = eidx[EE + base + t];
    }
    __syncthreads();

    for (int idx = t; idx < 6 * ROWS; idx += TB) {
        int c = idx / ROWS, r = idx % ROWS;
        EA[c * RS + r] = (c < 3) ? node_pos[(size_t)ssrc[r] * 3 + c]
                                 : grid_pos[(size_t)stgt[r] * 3 + (c - 3)];
    }
    __syncthreads();

    ull acc[32];
    float C[8][8];

    // L1: edge MLP hidden (K=6)
    init_acc(acc, em_b1, cbase);
    gemm8x8<6>(EA, em_w1, cbase, rbase, acc);
    unpack_all(acc, C);
    silu_all(C);
    store_tile(C, A, cg, rbase);
    __syncthreads();

    // L2: ef (K=128, no activation)
    init_acc(acc, em_b2, cbase);
    gemm8x8<H>(A, em_w2, cbase, rbase, acc);
    unpack_all(acc, C);
    __syncthreads();
    store_tile(C, A, cg, rbase);
    __syncthreads();

    // L3: m = silu(ef@mm_w1_bot + nf2[src] + mm_b1)
    init_acc(acc, mm_b1, cbase);
    gemm8x8<H>(A, mm_w1 + (size_t)H * H, cbase, rbase, acc);
    unpack_all(acc, C);
    #pragma unroll
    for (int rr = 0; rr < 8; rr++) {
        const float* nsrc = g_nf2 + (size_t)ssrc[rbase + rr] * H + cbase;
        float4 n0 = *reinterpret_cast<const float4*>(nsrc);
        float4 n1 = *reinterpret_cast<const float4*>(nsrc + 4);
        C[0][rr] += n0.x; C[1][rr] += n0.y; C[2][rr] += n0.z; C[3][rr] += n0.w;
        C[4][rr] += n1.x; C[5][rr] += n1.y; C[6][rr] += n1.z; C[7][rr] += n1.w;
    }
    silu_all(C);
    __syncthreads();
    store_tile(C, A, cg, rbase);
    __syncthreads();

    // L4: msg = m @ mm_w2 + mm_b2  -> scatter straight from registers
    init_acc(acc, mm_b2, cbase);
    gemm8x8<H>(A, mm_w2, cbase, rbase, acc);
    unpack_all(acc, C);
    #pragma unroll
    for (int rr = 0; rr < 8; rr++) {
        float* dst = g_agg + (size_t)stgt[rbase + rr] * H + cbase;
        asm volatile("red.global.add.v4.f32 [%0], {%1,%2,%3,%4};"
                     :: "l"(dst), "f"(C[0][rr]), "f"(C[1][rr]), "f"(C[2][rr]), "f"(C[3][rr])
                     : "memory");
        asm volatile("red.global.add.v4.f32 [%0], {%1,%2,%3,%4};"
                     :: "l"(dst + 4), "f"(C[4][rr]), "f"(C[5][rr]), "f"(C[6][rr]), "f"(C[7][rr])
                     : "memory");
    }
}

// ---------------------------------------------------------------------------
// Update MLP on mean-aggregated features -> output [G,128]
// ---------------------------------------------------------------------------
__global__ __launch_bounds__(TB, 3) void update_kernel(
    const float* __restrict__ w1, const float* __restrict__ b1,
    const float* __restrict__ w2, const float* __restrict__ b2,
    float* __restrict__ out)
{
    __shared__ __align__(16) float A[H * RS];
    __shared__ float sc[ROWS];
    const int base = blockIdx.x * ROWS;
    const int t = threadIdx.x;
    const int cg = t & 15, rg = t >> 4;
    const int cbase = cg * 8, rbase = rg * 8;

    if (t < ROWS) {
        float c = g_cnt[base + t];
        sc[t] = 1.0f / fmaxf(c, 1.0f);
    }
    __syncthreads();

    for (int idx = t; idx < ROWS * H; idx += TB) {
        int row = idx >> 7, col = idx & 127;
        A[col * RS + row] = g_agg[(size_t)(base + row) * H + col] * sc[row];
    }
    __syncthreads();

    ull acc[32];
    float C[8][8];

    init_acc(acc, b1, cbase);
    gemm8x8<H>(A, w1, cbase, rbase, acc);
    unpack_all(acc, C);
    silu_all(C);
    __syncthreads();
    store_tile(C, A, cg, rbase);
    __syncthreads();

    init_acc(acc, b2, cbase);
    gemm8x8<H>(A, w2, cbase, rbase, acc);
    unpack_all(acc, C);
    #pragma unroll
    for (int rr = 0; rr < 8; rr++) {
        float* dst = out + (size_t)(base + rbase + rr) * H + cbase;
        *reinterpret_cast<float4*>(dst)     = make_float4(C[0][rr], C[1][rr], C[2][rr], C[3][rr]);
        *reinterpret_cast<float4*>(dst + 4) = make_float4(C[4][rr], C[5][rr], C[6][rr], C[7][rr]);
    }
}

// ---------------------------------------------------------------------------
// Launch
// ---------------------------------------------------------------------------
extern "C" void kernel_launch(void* const* d_in, const int* in_sizes, int n_in,
                              void* d_out, int out_size) {
    const float* node_features = (const float*)d_in[0];
    const float* node_pos      = (const float*)d_in[1];
    const float* grid_pos      = (const float*)d_in[2];
    const int*   edge_index    = (const int*)d_in[3];
    const float* nm_w1 = (const float*)d_in[4];
    const float* nm_b1 = (const float*)d_in[5];
    const float* nm_w2 = (const float*)d_in[6];
    const float* nm_b2 = (const float*)d_in[7];
    const float* em_w1 = (const float*)d_in[8];
    const float* em_b1 = (const float*)d_in[9];
    const float* em_w2 = (const float*)d_in[10];
    const float* em_b2 = (const float*)d_in[11];
    const float* mm_w1 = (const float*)d_in[12];
    const float* mm_b1 = (const float*)d_in[13];
    const float* mm_w2 = (const float*)d_in[14];
    const float* mm_b2 = (const float*)d_in[15];
    const float* um_w1 = (const float*)d_in[16];
    const float* um_b1 = (const float*)d_in[17];
    const float* um_w2 = (const float*)d_in[18];
    const float* um_b2 = (const float*)d_in[19];
    float* out = (float*)d_out;

    zero_kernel<<<1024, 256>>>();

    // nf2 = (silu(x@nm_w1+b1)@nm_w2+b2) @ mm_w1_top   [N,128]
    node_kernel<<<NN / ROWS, TB>>>(node_features, nm_w1, nm_b1, nm_w2, nm_b2, mm_w1);

    count_kernel<<<(EE + 255) / 256, 256>>>(edge_index);

    // fused edge pipeline + scatter
    edge_kernel<<<EE / ROWS, TB>>>(edge_index, node_pos, grid_pos,
                                   em_w1, em_b1, em_w2, em_b2,
                                   mm_w1, mm_b1, mm_w2, mm_b2);

    // update MLP on mean-aggregated features
    update_kernel<<<GG / ROWS, TB>>>(um_w1, um_b1, um_w2, um_b2, out);
}

// round 16
// speedup vs baseline: 1.2115x; 1.0469x over previous
#include <cuda_runtime.h>
#include <cuda_bf16.h>
#include <cstdint>

#define H    128
#define NN   65536
#define GG   32768
#define EE   600000
#define TB   128        // 4 warps
#define MT   64         // rows per block tile
#define AW   68         // activation row stride in u32 (=136 bf16)
#define WSTRIDE 136     // weight row stride in bf16 (pad 128->136)
#define WBYTES  34816   // 128*136*2
#define ACT_BYTES 17408 // 64*68*4
#define MSGS 132        // msg row stride in floats

// dynamic smem layout: [Ah 17408][Al 17408][W 34816][aux 4096]
#define SMEM_N (2*ACT_BYTES + WBYTES)          // 69632 (node/update)
#define SMEM_E (SMEM_N + 4096)                 // 73728 (edge)

__device__ __align__(16) float g_nf2[(size_t)NN * H];
__device__ __align__(16) float g_agg[(size_t)GG * H];
__device__ float g_cnt[GG];
// pre-transposed bf16 weights [mat][hi/lo]: B layout [n][k] padded to 136
// 0 nm_w1, 1 nm_w2, 2 mm_w1_top, 3 em_w2, 4 mm_w1_bot, 5 mm_w2, 6 um_w1, 7 um_w2
__device__ __align__(16) unsigned char g_w[8][2][WBYTES];

// ---------------------------------------------------------------------------
__device__ __forceinline__ uint32_t smem_to_u32(const void* p) {
    uint32_t a;
    asm("{ .reg .u64 t; cvta.to.shared.u64 t, %1; cvt.u32.u64 %0, t; }" : "=r"(a) : "l"(p));
    return a;
}
__device__ __forceinline__ float silu_f(float x) { return x / (1.0f + __expf(-x)); }

__device__ __forceinline__ void bf16_split_pack(float v0, float v1, uint32_t& hi, uint32_t& lo) {
    __nv_bfloat16 h0 = __float2bfloat16(v0);
    __nv_bfloat16 h1 = __float2bfloat16(v1);
    __nv_bfloat16 l0 = __float2bfloat16(v0 - __bfloat162float(h0));
    __nv_bfloat16 l1 = __float2bfloat16(v1 - __bfloat162float(h1));
    hi = (uint32_t)__bfloat16_as_ushort(h0) | ((uint32_t)__bfloat16_as_ushort(h1) << 16);
    lo = (uint32_t)__bfloat16_as_ushort(l0) | ((uint32_t)__bfloat16_as_ushort(l1) << 16);
}

#define LDSM4(r0, r1, r2, r3, addr) \
    asm volatile("ldmatrix.sync.aligned.m8n8.x4.shared.b16 {%0,%1,%2,%3}, [%4];" \
                 : "=r"(r0), "=r"(r1), "=r"(r2), "=r"(r3) : "r"(addr))
#define LDSM2(r0, r1, addr) \
    asm volatile("ldmatrix.sync.aligned.m8n8.x2.shared.b16 {%0,%1}, [%2];" \
                 : "=r"(r0), "=r"(r1) : "r"(addr))
#define MMA4(c, A0, A1, A2, A3, B0, B1) \
    asm volatile("mma.sync.aligned.m16n8k16.row.col.f32.bf16.bf16.f32 " \
                 "{%0,%1,%2,%3}, {%4,%5,%6,%7}, {%8,%9}, {%0,%1,%2,%3};" \
                 : "+f"((c)[0]), "+f"((c)[1]), "+f"((c)[2]), "+f"((c)[3]) \
                 : "r"(A0), "r"(A1), "r"(A2), "r"(A3), "r"(B0), "r"(B1))

// ---------------------------------------------------------------------------
// One K=128 layer on HMMA: acc += Ah*Wh + Al*Wh + Ah*Wl (bf16-split fp32)
// Ah/Al: smem [64][136] bf16 (row=tile row, col=k).  W staged [128 n][136 k] bf16.
// Warp strip: rows [m0, m0+16), all 128 cols; acc[nt][4] = m16n8 tile nt.
// ---------------------------------------------------------------------------
__device__ __forceinline__ void mma_sweeps(uint32_t ahb, uint32_t alb, uint32_t wb,
                                           const unsigned char* __restrict__ wh,
                                           const unsigned char* __restrict__ wl,
                                           float4* smW4, int tid, int lane, int m0,
                                           float (&acc)[16][4]) {
    const int a_row = m0 + (lane & 7) + ((lane >> 3) & 1) * 8;
    const int a_k   = ((lane >> 4) & 1) * 8;
    const int b_row = lane & 7;
    const int b_k   = ((lane >> 3) & 1) * 8;

    for (int i = tid; i < WBYTES / 16; i += TB)
        smW4[i] = reinterpret_cast<const float4*>(wh)[i];
    __syncthreads();

    #pragma unroll 1
    for (int kc = 0; kc < 8; kc++) {
        uint32_t aH = ahb + (uint32_t)((a_row * WSTRIDE + kc * 16 + a_k) * 2);
        uint32_t aL = alb + (uint32_t)((a_row * WSTRIDE + kc * 16 + a_k) * 2);
        uint32_t h0, h1, h2, h3, l0, l1, l2, l3;
        LDSM4(h0, h1, h2, h3, aH);
        LDSM4(l0, l1, l2, l3, aL);
        #pragma unroll
        for (int nt = 0; nt < 16; nt++) {
            uint32_t aB = wb + (uint32_t)(((nt * 8 + b_row) * WSTRIDE + kc * 16 + b_k) * 2);
            uint32_t b0, b1;
            LDSM2(b0, b1, aB);
            MMA4(acc[nt], h0, h1, h2, h3, b0, b1);
            MMA4(acc[nt], l0, l1, l2, l3, b0, b1);
        }
    }
    __syncthreads();

    for (int i = tid; i < WBYTES / 16; i += TB)
        smW4[i] = reinterpret_cast<const float4*>(wl)[i];
    __syncthreads();

    #pragma unroll 1
    for (int kc = 0; kc < 8; kc++) {
        uint32_t aH = ahb + (uint32_t)((a_row * WSTRIDE + kc * 16 + a_k) * 2);
        uint32_t h0, h1, h2, h3;
        LDSM4(h0, h1, h2, h3, aH);
        #pragma unroll
        for (int nt = 0; nt < 16; nt++) {
            uint32_t aB = wb + (uint32_t)(((nt * 8 + b_row) * WSTRIDE + kc * 16 + b_k) * 2);
            uint32_t b0, b1;
            LDSM2(b0, b1, aB);
            MMA4(acc[nt], h0, h1, h2, h3, b0, b1);
        }
    }
    __syncthreads();   // all warps done with Ah/Al + W
}

__device__ __forceinline__ void acc_zero(float (&acc)[16][4]) {
    #pragma unroll
    for (int nt = 0; nt < 16; nt++) {
        acc[nt][0] = 0.f; acc[nt][1] = 0.f; acc[nt][2] = 0.f; acc[nt][3] = 0.f;
    }
}

// D fragment: d0,d1 = (row m0+g, cols nt*8+tg*2,+1); d2,d3 = row m0+g+8.
__device__ __forceinline__ void epi_act(float (&acc)[16][4], uint32_t* Ah, uint32_t* Al,
                                        const float* bias, const float* ex0, const float* ex1,
                                        bool do_silu, int m0, int lane) {
    int g = lane >> 2, tg = lane & 3;
    int r0 = m0 + g, r1 = m0 + g + 8;
    #pragma unroll
    for (int nt = 0; nt < 16; nt++) {
        int c = nt * 8 + tg * 2;
        float v0 = acc[nt][0], v1 = acc[nt][1], v2 = acc[nt][2], v3 = acc[nt][3];
        if (bias) {
            float2 b = *reinterpret_cast<const float2*>(bias + c);
            v0 += b.x; v1 += b.y; v2 += b.x; v3 += b.y;
        }
        if (ex0) {
            float2 e0 = *reinterpret_cast<const float2*>(ex0 + c);
            float2 e1 = *reinterpret_cast<const float2*>(ex1 + c);
            v0 += e0.x; v1 += e0.y; v2 += e1.x; v3 += e1.y;
        }
        if (do_silu) { v0 = silu_f(v0); v1 = silu_f(v1); v2 = silu_f(v2); v3 = silu_f(v3); }
        uint32_t h, l;
        bf16_split_pack(v0, v1, h, l);
        Ah[r0 * AW + nt * 4 + tg] = h; Al[r0 * AW + nt * 4 + tg] = l;
        bf16_split_pack(v2, v3, h, l);
        Ah[r1 * AW + nt * 4 + tg] = h; Al[r1 * AW + nt * 4 + tg] = l;
    }
}

__device__ __forceinline__ void epi_gmem(float (&acc)[16][4], float* outbase,
                                         const float* bias, int m0, int lane) {
    int g = lane >> 2, tg = lane & 3;
    int r0 = m0 + g, r1 = m0 + g + 8;
    #pragma unroll
    for (int nt = 0; nt < 16; nt++) {
        int c = nt * 8 + tg * 2;
        float bx = 0.f, by = 0.f;
        if (bias) { float2 b = *reinterpret_cast<const float2*>(bias + c); bx = b.x; by = b.y; }
        *reinterpret_cast<float2*>(outbase + (size_t)r0 * H + c) =
            make_float2(acc[nt][0] + bx, acc[nt][1] + by);
        *reinterpret_cast<float2*>(outbase + (size_t)r1 * H + c) =
            make_float2(acc[nt][2] + bx, acc[nt][3] + by);
    }
}

// ---------------------------------------------------------------------------
__global__ void zero_kernel() {
    size_t i = blockIdx.x * (size_t)blockDim.x + threadIdx.x;
    size_t stride = (size_t)gridDim.x * blockDim.x;
    size_t total4 = (size_t)GG * H / 4;
    float4 z = make_float4(0.f, 0.f, 0.f, 0.f);
    for (size_t p = i; p < total4; p += stride)
        reinterpret_cast<float4*>(g_agg)[p] = z;
    if (i < GG) g_cnt[i] = 0.f;
}

__global__ void count_kernel(const int* __restrict__ eidx) {
    int e = blockIdx.x * blockDim.x + threadIdx.x;
    if (e < EE) atomicAdd(&g_cnt[eidx[EE + e]], 1.0f);
}

// W[k][n] fp32 -> g_w[mat][0/1] as [n][136] bf16 hi/lo
__global__ void wprep_kernel(const float* w0, const float* w1, const float* w2, const float* w3,
                             const float* w4, const float* w5, const float* w6, const float* w7) {
    int i = blockIdx.x * blockDim.x + threadIdx.x;   // 0..16383
    const float* W;
    switch (blockIdx.y) {
        case 0: W = w0; break; case 1: W = w1; break; case 2: W = w2; break;
        case 3: W = w3; break; case 4: W = w4; break; case 5: W = w5; break;
        case 6: W = w6; break; default: W = w7; break;
    }
    int n = i & 127, k = i >> 7;
    float w = W[(size_t)k * H + n];
    __nv_bfloat16 hi = __float2bfloat16(w);
    __nv_bfloat16 lo = __float2bfloat16(w - __bfloat162float(hi));
    size_t off = ((size_t)n * WSTRIDE + k) * 2;
    *reinterpret_cast<__nv_bfloat16*>(g_w[blockIdx.y][0] + off) = hi;
    *reinterpret_cast<__nv_bfloat16*>(g_w[blockIdx.y][1] + off) = lo;
}

// ---------------------------------------------------------------------------
// Node: x -> silu(@nm_w1+b1) -> @nm_w2+b2 -> @mm_w1_top -> g_nf2
// ---------------------------------------------------------------------------
__global__ __launch_bounds__(TB) void node_tc(const float* __restrict__ x,
                                              const float* __restrict__ nm_b1,
                                              const float* __restrict__ nm_b2) {
    extern __shared__ __align__(16) char dsm[];
    uint32_t* Ah = reinterpret_cast<uint32_t*>(dsm);
    uint32_t* Al = reinterpret_cast<uint32_t*>(dsm + ACT_BYTES);
    float4* smW4 = reinterpret_cast<float4*>(dsm + 2 * ACT_BYTES);
    const int tid = threadIdx.x, lane = tid & 31, wid = tid >> 5;
    const int m0 = wid * 16;
    const int base = blockIdx.x * MT;
    uint32_t ahb = smem_to_u32(Ah), alb = smem_to_u32(Al), wb = smem_to_u32(smW4);

    {   // input: fp32 -> bf16 hi/lo act tile
        int row = tid >> 1, hf = tid & 1;
        const float4* xr = reinterpret_cast<const float4*>(x + (size_t)(base + row) * H + hf * 64);
        #pragma unroll
        for (int i = 0; i < 16; i++) {
            float4 v = xr[i];
            uint32_t h, l;
            int w0 = row * AW + hf * 32 + 2 * i;
            bf16_split_pack(v.x, v.y, h, l); Ah[w0] = h; Al[w0] = l;
            bf16_split_pack(v.z, v.w, h, l); Ah[w0 + 1] = h; Al[w0 + 1] = l;
        }
    }

    float acc[16][4];
    acc_zero(acc);
    mma_sweeps(ahb, alb, wb, g_w[0][0], g_w[0][1], smW4, tid, lane, m0, acc);
    epi_act(acc, Ah, Al, nm_b1, nullptr, nullptr, true, m0, lane);

    acc_zero(acc);
    mma_sweeps(ahb, alb, wb, g_w[1][0], g_w[1][1], smW4, tid, lane, m0, acc);
    epi_act(acc, Ah, Al, nm_b2, nullptr, nullptr, false, m0, lane);

    acc_zero(acc);
    mma_sweeps(ahb, alb, wb, g_w[2][0], g_w[2][1], smW4, tid, lane, m0, acc);
    epi_gmem(acc, g_nf2 + (size_t)base * H, nullptr, m0, lane);
}

// ---------------------------------------------------------------------------
// Edge (64 edges/tile): ea(6)->silu (scalar) -> ef -> m=silu(ef@W+nf2[src]+b) -> msg -> scatter
// ---------------------------------------------------------------------------
__global__ __launch_bounds__(TB) void edge_tc(const int* __restrict__ eidx,
                                              const float* __restrict__ node_pos,
                                              const float* __restrict__ grid_pos,
                                              const float* __restrict__ em_w1,
                                              const float* __restrict__ em_b1,
                                              const float* __restrict__ em_b2,
                                              const float* __restrict__ mm_b1,
                                              const float* __restrict__ mm_b2) {
    extern __shared__ __align__(16) char dsm[];
    uint32_t* Ah = reinterpret_cast<uint32_t*>(dsm);
    uint32_t* Al = reinterpret_cast<uint32_t*>(dsm + ACT_BYTES);
    float4* smW4 = reinterpret_cast<float4*>(dsm + 2 * ACT_BYTES);
    int* ssrc  = reinterpret_cast<int*>(dsm + SMEM_N);
    int* stgt  = ssrc + 64;
    float* sW1 = reinterpret_cast<float*>(stgt + 64);
    float* sB1 = sW1 + 6 * H;
    float* msg = reinterpret_cast<float*>(smW4);   // reused after final sweep

    const int tid = threadIdx.x, lane = tid & 31, wid = tid >> 5;
    const int m0 = wid * 16;
    const int base = blockIdx.x * MT;
    uint32_t ahb = smem_to_u32(Ah), alb = smem_to_u32(Al), wb = smem_to_u32(smW4);

    if (tid < 64) { ssrc[tid] = eidx[base + tid]; stgt[tid] = eidx[EE + base + tid]; }
    for (int i = tid; i < 6 * H; i += TB) sW1[i] = em_w1[i];
    if (tid < H) sB1[tid] = em_b1[tid];
    __syncthreads();

    {   // L1 scalar (K=6): silu(ea @ em_w1 + b1) -> act tile
        int row = tid >> 1, hf = tid & 1;
        int s = ssrc[row], g = stgt[row];
        float ea0 = node_pos[(size_t)s * 3],     ea1 = node_pos[(size_t)s * 3 + 1];
        float ea2 = node_pos[(size_t)s * 3 + 2];
        float ea3 = grid_pos[(size_t)g * 3],     ea4 = grid_pos[(size_t)g * 3 + 1];
        float ea5 = grid_pos[(size_t)g * 3 + 2];
        #pragma unroll 4
        for (int j = 0; j < 64; j += 2) {
            int c = hf * 64 + j;
            float v0 = sB1[c], v1 = sB1[c + 1];
            v0 += ea0 * sW1[c] + ea1 * sW1[H + c] + ea2 * sW1[2 * H + c]
                + ea3 * sW1[3 * H + c] + ea4 * sW1[4 * H + c] + ea5 * sW1[5 * H + c];
            v1 += ea0 * sW1[c + 1] + ea1 * sW1[H + c + 1] + ea2 * sW1[2 * H + c + 1]
                + ea3 * sW1[3 * H + c + 1] + ea4 * sW1[4 * H + c + 1] + ea5 * sW1[5 * H + c + 1];
            uint32_t h, l;
            bf16_split_pack(silu_f(v0), silu_f(v1), h, l);
            int w0 = row * AW + c / 2;
            Ah[w0] = h; Al[w0] = l;
        }
    }

    float acc[16][4];
    // L2: ef = h @ em_w2 + b2
    acc_zero(acc);
    mma_sweeps(ahb, alb, wb, g_w[3][0], g_w[3][1], smW4, tid, lane, m0, acc);
    epi_act(acc, Ah, Al, em_b2, nullptr, nullptr, false, m0, lane);

    // L3: m = silu(ef @ mm_w1_bot + nf2[src] + mm_b1)
    acc_zero(acc);
    mma_sweeps(ahb, alb, wb, g_w[4][0], g_w[4][1], smW4, tid, lane, m0, acc);
    {
        int g = lane >> 2;
        const float* ex0 = g_nf2 + (size_t)ssrc[m0 + g] * H;
        const float* ex1 = g_nf2 + (size_t)ssrc[m0 + g + 8] * H;
        epi_act(acc, Ah, Al, mm_b1, ex0, ex1, true, m0, lane);
    }

    // L4: msg = m @ mm_w2 + b2 -> stage in smem (reuse W buffer)
    acc_zero(acc);
    mma_sweeps(ahb, alb, wb, g_w[5][0], g_w[5][1], smW4, tid, lane, m0, acc);
    {
        int g = lane >> 2, tg = lane & 3;
        int r0 = m0 + g, r1 = m0 + g + 8;
        #pragma unroll
        for (int nt = 0; nt < 16; nt++) {
            int c = nt * 8 + tg * 2;
            float2 b = *reinterpret_cast<const float2*>(mm_b2 + c);
            *reinterpret_cast<float2*>(msg + r0 * MSGS + c) =
                make_float2(acc[nt][0] + b.x, acc[nt][1] + b.y);
            *reinterpret_cast<float2*>(msg + r1 * MSGS + c) =
                make_float2(acc[nt][2] + b.x, acc[nt][3] + b.y);
        }
    }
    __syncthreads();

    // scatter: 64 rows x 32 float4 chunks via vector atomics
    for (int i = tid; i < MT * 32; i += TB) {
        int row = i >> 5, c4 = (i & 31) * 4;
        float4 v = *reinterpret_cast<float4*>(msg + row * MSGS + c4);
        float* dst = g_agg + (size_t)stgt[row] * H + c4;
        asm volatile("red.global.add.v4.f32 [%0], {%1,%2,%3,%4};"
                     :: "l"(dst), "f"(v.x), "f"(v.y), "f"(v.z), "f"(v.w) : "memory");
    }
}

// ---------------------------------------------------------------------------
// Update: agg/cnt -> silu(@um_w1+b1) -> @um_w2+b2 -> out
// ---------------------------------------------------------------------------
__global__ __launch_bounds__(TB) void update_tc(const float* __restrict__ um_b1,
                                                const float* __restrict__ um_b2,
                                                float* __restrict__ out) {
    extern __shared__ __align__(16) char dsm[];
    uint32_t* Ah = reinterpret_cast<uint32_t*>(dsm);
    uint32_t* Al = reinterpret_cast<uint32_t*>(dsm + ACT_BYTES);
    float4* smW4 = reinterpret_cast<float4*>(dsm + 2 * ACT_BYTES);
    const int tid = threadIdx.x, lane = tid & 31, wid = tid >> 5;
    const int m0 = wid * 16;
    const int base = blockIdx.x * MT;
    uint32_t ahb = smem_to_u32(Ah), alb = smem_to_u32(Al), wb = smem_to_u32(smW4);

    {
        int row = tid >> 1, hf = tid & 1;
        float sc = 1.0f / fmaxf(g_cnt[base + row], 1.0f);
        const float4* ar = reinterpret_cast<const float4*>(g_agg + (size_t)(base + row) * H + hf * 64);
        #pragma unroll
        for (int i = 0; i < 16; i++) {
            float4 v = ar[i];
            uint32_t h, l;
            int w0 = row * AW + hf * 32 + 2 * i;
            bf16_split_pack(v.x * sc, v.y * sc, h, l); Ah[w0] = h; Al[w0] = l;
            bf16_split_pack(v.z * sc, v.w * sc, h, l); Ah[w0 + 1] = h; Al[w0 + 1] = l;
        }
    }

    float acc[16][4];
    acc_zero(acc);
    mma_sweeps(ahb, alb, wb, g_w[6][0], g_w[6][1], smW4, tid, lane, m0, acc);
    epi_act(acc, Ah, Al, um_b1, nullptr, nullptr, true, m0, lane);

    acc_zero(acc);
    mma_sweeps(ahb, alb, wb, g_w[7][0], g_w[7][1], smW4, tid, lane, m0, acc);
    epi_gmem(acc, out + (size_t)base * H, um_b2, m0, lane);
}

// ---------------------------------------------------------------------------
extern "C" void kernel_launch(void* const* d_in, const int* in_sizes, int n_in,
                              void* d_out, int out_size) {
    const float* node_features = (const float*)d_in[0];
    const float* node_pos      = (const float*)d_in[1];
    const float* grid_pos      = (const float*)d_in[2];
    const int*   edge_index    = (const int*)d_in[3];
    const float* nm_w1 = (const float*)d_in[4];
    const float* nm_b1 = (const float*)d_in[5];
    const float* nm_w2 = (const float*)d_in[6];
    const float* nm_b2 = (const float*)d_in[7];
    const float* em_w1 = (const float*)d_in[8];
    const float* em_b1 = (const float*)d_in[9];
    const float* em_w2 = (const float*)d_in[10];
    const float* em_b2 = (const float*)d_in[11];
    const float* mm_w1 = (const float*)d_in[12];
    const float* mm_b1 = (const float*)d_in[13];
    const float* mm_w2 = (const float*)d_in[14];
    const float* mm_b2 = (const float*)d_in[15];
    const float* um_w1 = (const float*)d_in[16];
    const float* um_b1 = (const float*)d_in[17];
    const float* um_w2 = (const float*)d_in[18];
    const float* um_b2 = (const float*)d_in[19];
    float* out = (float*)d_out;

    cudaFuncSetAttribute(node_tc,   cudaFuncAttributeMaxDynamicSharedMemorySize, SMEM_N);
    cudaFuncSetAttribute(edge_tc,   cudaFuncAttributeMaxDynamicSharedMemorySize, SMEM_E);
    cudaFuncSetAttribute(update_tc, cudaFuncAttributeMaxDynamicSharedMemorySize, SMEM_N);

    zero_kernel<<<1024, 256>>>();
    wprep_kernel<<<dim3(128, 8), 128>>>(nm_w1, nm_w2, mm_w1, em_w2,
                                        mm_w1 + (size_t)H * H, mm_w2, um_w1, um_w2);
    count_kernel<<<(EE + 255) / 256, 256>>>(edge_index);

    node_tc<<<NN / MT, TB, SMEM_N>>>(node_features, nm_b1, nm_b2);
    edge_tc<<<EE / MT, TB, SMEM_E>>>(edge_index, node_pos, grid_pos,
                                     em_w1, em_b1, em_b2, mm_b1, mm_b2);
    update_tc<<<GG / MT, TB, SMEM_N>>>(um_b1, um_b2, out);
}

// round 17
// speedup vs baseline: 2.6061x; 2.1511x over previous
#include <cuda_runtime.h>
#include <cuda_bf16.h>
#include <cstdint>

#define H    128
#define NN   65536
#define GG   32768
#define EE   600000
#define TB   128        // 4 warps
#define MT   64         // rows per block tile
#define AW   68         // activation row stride in u32 (=136 bf16)
#define ACT_BYTES 17408 // 64*68*4
#define MSGS 132        // msg row stride in floats

#define SMEM_N (2*ACT_BYTES)          // 34816 (node/update)
#define SMEM_E (SMEM_N + 4096)        // 38912 (edge: + ssrc/stgt/sW1/sB1)

__device__ __align__(16) float g_nf2[(size_t)NN * H];
__device__ __align__(16) float g_agg[(size_t)GG * H];
__device__ float g_cnt[GG];
// fragment-linear bf16 weights: [mat][hi/lo][kc*16+nt][lane] as uint2 (b0,b1)
// 0 nm_w1, 1 nm_w2, 2 mm_w1_top, 3 em_w2, 4 mm_w1_bot, 5 mm_w2, 6 um_w1, 7 um_w2
__device__ __align__(16) uint2 g_wf[8][2][4096];

// ---------------------------------------------------------------------------
__device__ __forceinline__ uint32_t smem_to_u32(const void* p) {
    uint32_t a;
    asm("{ .reg .u64 t; cvta.to.shared.u64 t, %1; cvt.u32.u64 %0, t; }" : "=r"(a) : "l"(p));
    return a;
}
__device__ __forceinline__ float silu_f(float x) { return x / (1.0f + __expf(-x)); }

__device__ __forceinline__ uint32_t pack_bf2(float a, float b) {
    return (uint32_t)__bfloat16_as_ushort(__float2bfloat16(a)) |
           ((uint32_t)__bfloat16_as_ushort(__float2bfloat16(b)) << 16);
}
__device__ __forceinline__ void bf16_split_pack(float v0, float v1, uint32_t& hi, uint32_t& lo) {
    __nv_bfloat16 h0 = __float2bfloat16(v0);
    __nv_bfloat16 h1 = __float2bfloat16(v1);
    float r0 = v0 - __bfloat162float(h0);
    float r1 = v1 - __bfloat162float(h1);
    hi = (uint32_t)__bfloat16_as_ushort(h0) | ((uint32_t)__bfloat16_as_ushort(h1) << 16);
    lo = pack_bf2(r0, r1);
}

#define LDSM4(r0, r1, r2, r3, addr) \
    asm volatile("ldmatrix.sync.aligned.m8n8.x4.shared.b16 {%0,%1,%2,%3}, [%4];" \
                 : "=r"(r0), "=r"(r1), "=r"(r2), "=r"(r3) : "r"(addr))
#define MMA4(c, A0, A1, A2, A3, B0, B1) \
    asm volatile("mma.sync.aligned.m16n8k16.row.col.f32.bf16.bf16.f32 " \
                 "{%0,%1,%2,%3}, {%4,%5,%6,%7}, {%8,%9}, {%0,%1,%2,%3};" \
                 : "+f"((c)[0]), "+f"((c)[1]), "+f"((c)[2]), "+f"((c)[3]) \
                 : "r"(A0), "r"(A1), "r"(A2), "r"(A3), "r"(B0), "r"(B1))

// ---------------------------------------------------------------------------
// One K=128 layer: acc += Ah*Wh + Al*Wh + Ah*Wl.
// A: smem [64][136] bf16 via ldmatrix (warp reads ONLY its own 16-row strip).
// B: gmem fragment-linear uint2 per (kc,nt,lane) — coalesced LDG.64, L1/L2-hot.
// ---------------------------------------------------------------------------
__device__ __forceinline__ void mma_layer(uint32_t ahb, uint32_t alb,
                                          const uint2* __restrict__ wh,
                                          const uint2* __restrict__ wl,
                                          int lane, int m0, float (&acc)[16][4]) {
    const int a_row = m0 + (lane & 7) + ((lane >> 3) & 1) * 8;
    const int a_k   = ((lane >> 4) & 1) * 8;
    #pragma unroll 1
    for (int kc = 0; kc < 8; kc++) {
        uint32_t aH = ahb + (uint32_t)((a_row * 136 + kc * 16 + a_k) * 2);
        uint32_t aL = alb + (uint32_t)((a_row * 136 + kc * 16 + a_k) * 2);
        uint32_t h0, h1, h2, h3, l0, l1, l2, l3;
        LDSM4(h0, h1, h2, h3, aH);
        LDSM4(l0, l1, l2, l3, aL);
        const uint2* ph = wh + kc * 512 + lane;
        const uint2* pl = wl + kc * 512 + lane;
        #pragma unroll
        for (int nt = 0; nt < 16; nt++) {
            uint2 bh = ph[nt * 32];
            uint2 bl = pl[nt * 32];
            MMA4(acc[nt], h0, h1, h2, h3, bh.x, bh.y);
            MMA4(acc[nt], l0, l1, l2, l3, bh.x, bh.y);
            MMA4(acc[nt], h0, h1, h2, h3, bl.x, bl.y);
        }
    }
}

__device__ __forceinline__ void acc_zero(float (&acc)[16][4]) {
    #pragma unroll
    for (int nt = 0; nt < 16; nt++) {
        acc[nt][0] = 0.f; acc[nt][1] = 0.f; acc[nt][2] = 0.f; acc[nt][3] = 0.f;
    }
}

// D frag: d0,d1 = (row m0+g, col nt*8+tg*2,+1); d2,d3 = row m0+g+8. Strip-local.
__device__ __forceinline__ void epi_act(float (&acc)[16][4], uint32_t* Ah, uint32_t* Al,
                                        const float* bias, const float* ex0, const float* ex1,
                                        bool do_silu, int m0, int lane) {
    int g = lane >> 2, tg = lane & 3;
    int r0 = m0 + g, r1 = m0 + g + 8;
    #pragma unroll
    for (int nt = 0; nt < 16; nt++) {
        int c = nt * 8 + tg * 2;
        float v0 = acc[nt][0], v1 = acc[nt][1], v2 = acc[nt][2], v3 = acc[nt][3];
        if (bias) {
            float2 b = *reinterpret_cast<const float2*>(bias + c);
            v0 += b.x; v1 += b.y; v2 += b.x; v3 += b.y;
        }
        if (ex0) {
            float2 e0 = *reinterpret_cast<const float2*>(ex0 + c);
            float2 e1 = *reinterpret_cast<const float2*>(ex1 + c);
            v0 += e0.x; v1 += e0.y; v2 += e1.x; v3 += e1.y;
        }
        if (do_silu) { v0 = silu_f(v0); v1 = silu_f(v1); v2 = silu_f(v2); v3 = silu_f(v3); }
        uint32_t h, l;
        bf16_split_pack(v0, v1, h, l);
        Ah[r0 * AW + nt * 4 + tg] = h; Al[r0 * AW + nt * 4 + tg] = l;
        bf16_split_pack(v2, v3, h, l);
        Ah[r1 * AW + nt * 4 + tg] = h; Al[r1 * AW + nt * 4 + tg] = l;
    }
}

__device__ __forceinline__ void epi_gmem(float (&acc)[16][4], float* outbase,
                                         const float* bias, int m0, int lane) {
    int g = lane >> 2, tg = lane & 3;
    int r0 = m0 + g, r1 = m0 + g + 8;
    #pragma unroll
    for (int nt = 0; nt < 16; nt++) {
        int c = nt * 8 + tg * 2;
        float bx = 0.f, by = 0.f;
        if (bias) { float2 b = *reinterpret_cast<const float2*>(bias + c); bx = b.x; by = b.y; }
        *reinterpret_cast<float2*>(outbase + (size_t)r0 * H + c) =
            make_float2(acc[nt][0] + bx, acc[nt][1] + by);
        *reinterpret_cast<float2*>(outbase + (size_t)r1 * H + c) =
            make_float2(acc[nt][2] + bx, acc[nt][3] + by);
    }
}

// ---------------------------------------------------------------------------
__global__ void zero_kernel() {
    size_t i = blockIdx.x * (size_t)blockDim.x + threadIdx.x;
    size_t stride = (size_t)gridDim.x * blockDim.x;
    size_t total4 = (size_t)GG * H / 4;
    float4 z = make_float4(0.f, 0.f, 0.f, 0.f);
    for (size_t p = i; p < total4; p += stride)
        reinterpret_cast<float4*>(g_agg)[p] = z;
    if (i < GG) g_cnt[i] = 0.f;
}

__global__ void count_kernel(const int* __restrict__ eidx) {
    int e = blockIdx.x * blockDim.x + threadIdx.x;
    if (e < EE) atomicAdd(&g_cnt[eidx[EE + e]], 1.0f);
}

// W[k][n] fp32 -> fragment-linear uint2 (replicates the validated ldmatrix mapping):
// b0(lane) = W[kc*16 + (lane&3)*2 + {0,1}][nt*8 + lane/4]; b1 = same at k+8.
__global__ void wprep_kernel(const float* w0, const float* w1, const float* w2, const float* w3,
                             const float* w4, const float* w5, const float* w6, const float* w7) {
    int idx = blockIdx.x * blockDim.x + threadIdx.x;   // 0..4095
    const float* W;
    switch (blockIdx.y) {
        case 0: W = w0; break; case 1: W = w1; break; case 2: W = w2; break;
        case 3: W = w3; break; case 4: W = w4; break; case 5: W = w5; break;
        case 6: W = w6; break; default: W = w7; break;
    }
    int lane = idx & 31, nt = (idx >> 5) & 15, kc = idx >> 9;
    int n  = nt * 8 + (lane >> 2);
    int k0 = kc * 16 + (lane & 3) * 2;
    float wa = W[(size_t)k0 * H + n],       wb = W[(size_t)(k0 + 1) * H + n];
    float wc = W[(size_t)(k0 + 8) * H + n], wd = W[(size_t)(k0 + 9) * H + n];
    uint32_t h0, l0, h1, l1;
    bf16_split_pack(wa, wb, h0, l0);
    bf16_split_pack(wc, wd, h1, l1);
    g_wf[blockIdx.y][0][idx] = make_uint2(h0, h1);
    g_wf[blockIdx.y][1][idx] = make_uint2(l0, l1);
}

// ---------------------------------------------------------------------------
// Node: x -> silu(@nm_w1+b1) -> @nm_w2+b2 -> @mm_w1_top -> g_nf2
// One __syncthreads total; layers are warp-strip-local.
// ---------------------------------------------------------------------------
__global__ __launch_bounds__(TB) void node_tc(const float* __restrict__ x,
                                              const float* __restrict__ nm_b1,
                                              const float* __restrict__ nm_b2) {
    extern __shared__ __align__(16) char dsm[];
    uint32_t* Ah = reinterpret_cast<uint32_t*>(dsm);
    uint32_t* Al = reinterpret_cast<uint32_t*>(dsm + ACT_BYTES);
    const int tid = threadIdx.x, lane = tid & 31, wid = tid >> 5;
    const int m0 = wid * 16;
    const int base = blockIdx.x * MT;
    uint32_t ahb = smem_to_u32(Ah), alb = smem_to_u32(Al);

    {   // input fp32 -> bf16 hi/lo act tile
        int row = tid >> 1, hf = tid & 1;
        const float4* xr = reinterpret_cast<const float4*>(x + (size_t)(base + row) * H + hf * 64);
        #pragma unroll
        for (int i = 0; i < 16; i++) {
            float4 v = xr[i];
            uint32_t h, l;
            int w0 = row * AW + hf * 32 + 2 * i;
            bf16_split_pack(v.x, v.y, h, l); Ah[w0] = h; Al[w0] = l;
            bf16_split_pack(v.z, v.w, h, l); Ah[w0 + 1] = h; Al[w0 + 1] = l;
        }
    }
    __syncthreads();

    float acc[16][4];
    acc_zero(acc);
    mma_layer(ahb, alb, g_wf[0][0], g_wf[0][1], lane, m0, acc);
    epi_act(acc, Ah, Al, nm_b1, nullptr, nullptr, true, m0, lane);

    acc_zero(acc);
    mma_layer(ahb, alb, g_wf[1][0], g_wf[1][1], lane, m0, acc);
    epi_act(acc, Ah, Al, nm_b2, nullptr, nullptr, false, m0, lane);

    acc_zero(acc);
    mma_layer(ahb, alb, g_wf[2][0], g_wf[2][1], lane, m0, acc);
    epi_gmem(acc, g_nf2 + (size_t)base * H, nullptr, m0, lane);
}

// ---------------------------------------------------------------------------
// Edge (64 edges/tile): ea(6)->silu (scalar) -> ef -> m=silu(ef@W+nf2[src]+b)
//   -> msg -> RED scatter
// ---------------------------------------------------------------------------
__global__ __launch_bounds__(TB) void edge_tc(const int* __restrict__ eidx,
                                              const float* __restrict__ node_pos,
                                              const float* __restrict__ grid_pos,
                                              const float* __restrict__ em_w1,
                                              const float* __restrict__ em_b1,
                                              const float* __restrict__ em_b2,
                                              const float* __restrict__ mm_b1,
                                              const float* __restrict__ mm_b2) {
    extern __shared__ __align__(16) char dsm[];
    uint32_t* Ah = reinterpret_cast<uint32_t*>(dsm);
    uint32_t* Al = reinterpret_cast<uint32_t*>(dsm + ACT_BYTES);
    int* ssrc  = reinterpret_cast<int*>(dsm + SMEM_N);
    int* stgt  = ssrc + 64;
    float* sW1 = reinterpret_cast<float*>(stgt + 64);
    float* sB1 = sW1 + 6 * H;
    float* msg = reinterpret_cast<float*>(dsm);   // aliases act tiles after L4

    const int tid = threadIdx.x, lane = tid & 31, wid = tid >> 5;
    const int m0 = wid * 16;
    const int base = blockIdx.x * MT;
    uint32_t ahb = smem_to_u32(Ah), alb = smem_to_u32(Al);

    if (tid < 64) { ssrc[tid] = eidx[base + tid]; stgt[tid] = eidx[EE + base + tid]; }
    for (int i = tid; i < 6 * H; i += TB) sW1[i] = em_w1[i];
    if (tid < H) sB1[tid] = em_b1[tid];
    __syncthreads();

    {   // L1 scalar (K=6): silu(ea @ em_w1 + b1) -> act tile (cross-strip writes)
        int row = tid >> 1, hf = tid & 1;
        int s = ssrc[row], g = stgt[row];
        float ea0 = node_pos[(size_t)s * 3],     ea1 = node_pos[(size_t)s * 3 + 1];
        float ea2 = node_pos[(size_t)s * 3 + 2];
        float ea3 = grid_pos[(size_t)g * 3],     ea4 = grid_pos[(size_t)g * 3 + 1];
        float ea5 = grid_pos[(size_t)g * 3 + 2];
        #pragma unroll 4
        for (int j = 0; j < 64; j += 2) {
            int c = hf * 64 + j;
            float v0 = sB1[c], v1 = sB1[c + 1];
            v0 += ea0 * sW1[c] + ea1 * sW1[H + c] + ea2 * sW1[2 * H + c]
                + ea3 * sW1[3 * H + c] + ea4 * sW1[4 * H + c] + ea5 * sW1[5 * H + c];
            v1 += ea0 * sW1[c + 1] + ea1 * sW1[H + c + 1] + ea2 * sW1[2 * H + c + 1]
                + ea3 * sW1[3 * H + c + 1] + ea4 * sW1[4 * H + c + 1] + ea5 * sW1[5 * H + c + 1];
            uint32_t h, l;
            bf16_split_pack(silu_f(v0), silu_f(v1), h, l);
            int w0 = row * AW + c / 2;
            Ah[w0] = h; Al[w0] = l;
        }
    }
    __syncthreads();

    float acc[16][4];
    // L2: ef = h @ em_w2 + b2
    acc_zero(acc);
    mma_layer(ahb, alb, g_wf[3][0], g_wf[3][1], lane, m0, acc);
    epi_act(acc, Ah, Al, em_b2, nullptr, nullptr, false, m0, lane);

    // L3: m = silu(ef @ mm_w1_bot + nf2[src] + mm_b1)
    acc_zero(acc);
    mma_layer(ahb, alb, g_wf[4][0], g_wf[4][1], lane, m0, acc);
    {
        int g = lane >> 2;
        const float* ex0 = g_nf2 + (size_t)ssrc[m0 + g] * H;
        const float* ex1 = g_nf2 + (size_t)ssrc[m0 + g + 8] * H;
        epi_act(acc, Ah, Al, mm_b1, ex0, ex1, true, m0, lane);
    }

    // L4: msg = m @ mm_w2 + b2
    acc_zero(acc);
    mma_layer(ahb, alb, g_wf[5][0], g_wf[5][1], lane, m0, acc);
    __syncthreads();    // all warps done reading act tiles; msg may alias them
    {
        int g = lane >> 2, tg = lane & 3;
        int r0 = m0 + g, r1 = m0 + g + 8;
        #pragma unroll
        for (int nt = 0; nt < 16; nt++) {
            int c = nt * 8 + tg * 2;
            float2 b = *reinterpret_cast<const float2*>(mm_b2 + c);
            *reinterpret_cast<float2*>(msg + r0 * MSGS + c) =
                make_float2(acc[nt][0] + b.x, acc[nt][1] + b.y);
            *reinterpret_cast<float2*>(msg + r1 * MSGS + c) =
                make_float2(acc[nt][2] + b.x, acc[nt][3] + b.y);
        }
    }
    __syncthreads();

    for (int i = tid; i < MT * 32; i += TB) {
        int row = i >> 5, c4 = (i & 31) * 4;
        float4 v = *reinterpret_cast<float4*>(msg + row * MSGS + c4);
        float* dst = g_agg + (size_t)stgt[row] * H + c4;
        asm volatile("red.global.add.v4.f32 [%0], {%1,%2,%3,%4};"
                     :: "l"(dst), "f"(v.x), "f"(v.y), "f"(v.z), "f"(v.w) : "memory");
    }
}

// ---------------------------------------------------------------------------
// Update: agg/cnt -> silu(@um_w1+b1) -> @um_w2+b2 -> out
// ---------------------------------------------------------------------------
__global__ __launch_bounds__(TB) void update_tc(const float* __restrict__ um_b1,
                                                const float* __restrict__ um_b2,
                                                float* __restrict__ out) {
    extern __shared__ __align__(16) char dsm[];
    uint32_t* Ah = reinterpret_cast<uint32_t*>(dsm);
    uint32_t* Al = reinterpret_cast<uint32_t*>(dsm + ACT_BYTES);
    const int tid = threadIdx.x, lane = tid & 31, wid = tid >> 5;
    const int m0 = wid * 16;
    const int base = blockIdx.x * MT;
    uint32_t ahb = smem_to_u32(Ah), alb = smem_to_u32(Al);

    {
        int row = tid >> 1, hf = tid & 1;
        float sc = 1.0f / fmaxf(g_cnt[base + row], 1.0f);
        const float4* ar = reinterpret_cast<const float4*>(g_agg + (size_t)(base + row) * H + hf * 64);
        #pragma unroll
        for (int i = 0; i < 16; i++) {
            float4 v = ar[i];
            uint32_t h, l;
            int w0 = row * AW + hf * 32 + 2 * i;
            bf16_split_pack(v.x * sc, v.y * sc, h, l); Ah[w0] = h; Al[w0] = l;
            bf16_split_pack(v.z * sc, v.w * sc, h, l); Ah[w0 + 1] = h; Al[w0 + 1] = l;
        }
    }
    __syncthreads();

    float acc[16][4];
    acc_zero(acc);
    mma_layer(ahb, alb, g_wf[6][0], g_wf[6][1], lane, m0, acc);
    epi_act(acc, Ah, Al, um_b1, nullptr, nullptr, true, m0, lane);

    acc_zero(acc);
    mma_layer(ahb, alb, g_wf[7][0], g_wf[7][1], lane, m0, acc);
    epi_gmem(acc, out + (size_t)base * H, um_b2, m0, lane);
}

// ---------------------------------------------------------------------------
extern "C" void kernel_launch(void* const* d_in, const int* in_sizes, int n_in,
                              void* d_out, int out_size) {
    const float* node_features = (const float*)d_in[0];
    const float* node_pos      = (const float*)d_in[1];
    const float* grid_pos      = (const float*)d_in[2];
    const int*   edge_index    = (const int*)d_in[3];
    const float* nm_w1 = (const float*)d_in[4];
    const float* nm_b1 = (const float*)d_in[5];
    const float* nm_w2 = (const float*)d_in[6];
    const float* nm_b2 = (const float*)d_in[7];
    const float* em_w1 = (const float*)d_in[8];
    const float* em_b1 = (const float*)d_in[9];
    const float* em_w2 = (const float*)d_in[10];
    const float* em_b2 = (const float*)d_in[11];
    const float* mm_w1 = (const float*)d_in[12];
    const float* mm_b1 = (const float*)d_in[13];
    const float* mm_w2 = (const float*)d_in[14];
    const float* mm_b2 = (const float*)d_in[15];
    const float* um_w1 = (const float*)d_in[16];
    const float* um_b1 = (const float*)d_in[17];
    const float* um_w2 = (const float*)d_in[18];
    const float* um_b2 = (const float*)d_in[19];
    float* out = (float*)d_out;

    cudaFuncSetAttribute(node_tc,   cudaFuncAttributeMaxDynamicSharedMemorySize, SMEM_N);
    cudaFuncSetAttribute(edge_tc,   cudaFuncAttributeMaxDynamicSharedMemorySize, SMEM_E);
    cudaFuncSetAttribute(update_tc, cudaFuncAttributeMaxDynamicSharedMemorySize, SMEM_N);

    zero_kernel<<<1024, 256>>>();
    wprep_kernel<<<dim3(32, 8), 128>>>(nm_w1, nm_w2, mm_w1, em_w2,
                                       mm_w1 + (size_t)H * H, mm_w2, um_w1, um_w2);
    count_kernel<<<(EE + 255) / 256, 256>>>(edge_index);

    node_tc<<<NN / MT, TB, SMEM_N>>>(node_features, nm_b1, nm_b2);
    edge_tc<<<EE / MT, TB, SMEM_E>>>(edge_index, node_pos, grid_pos,
                                     em_w1, em_b1, em_b2, mm_b1, mm_b2);
    update_tc<<<GG / MT, TB, SMEM_N>>>(um_b1, um_b2, out);
}